// round 11
// baseline (speedup 1.0000x reference)
#include <cuda_runtime.h>
#include <cstdint>

#define CC 64
#define HWN 262144
#define NB 256
#define FINE 32768             // 2^15 fine bins per channel (lambda ~ 4)
#define WBIN (1.0f / (float)FINE)
#define TILEB 2048
#define NT (FINE / TILEB)      // 16 tiles per channel

// ---------------- scratch ----------------------------------------------------------
__device__ int            g_nI, g_nJ;
__device__ int            g_minJ[CC];    // float bits (values >= 0 -> int order == float order)
__device__ int            g_maxJ[CC];
__device__ int            g_histJ[CC * NB];
__device__ int            g_cntI[CC * FINE];     // counts -> (in place) tile-local offsets (8MB)
__device__ int            g_cntJ[CC * FINE];     // fine counts of masked J (8MB)
__device__ int            g_tbase[CC * NT];      // per-tile totals (scanned in k_loss)
__device__ double         g_loss;
__device__ unsigned int   g_done;

static __device__ __forceinline__ int fbin(float x) {
    int b = (int)(x * (float)FINE);
    return b < 0 ? 0 : (b > FINE - 1 ? FINE - 1 : b);
}

// ---------------- K0: init ----------------------------------------------------------
__global__ void k_init() {
    int i = blockIdx.x * blockDim.x + threadIdx.x;   // CC*FINE/4 threads
    ((int4*)g_cntI)[i] = make_int4(0, 0, 0, 0);
    ((int4*)g_cntJ)[i] = make_int4(0, 0, 0, 0);
    if (i < CC * NB) g_histJ[i] = 0;
    if (i < CC) { g_minJ[i] = 0x7F800000; g_maxJ[i] = 0; }
    if (i == 0) { g_nI = 0; g_nJ = 0; g_loss = 0.0; g_done = 0u; }
}

// ---------------- K1: single pass over I,J,masks ------------------------------------
__global__ void k_pass1(const float4* __restrict__ I, const float4* __restrict__ J,
                        const int4* __restrict__ mI4, const int4* __restrict__ mJ4) {
    int c = blockIdx.y;
    int i = blockIdx.x * blockDim.x + threadIdx.x;     // HWN/8 per channel
    int base = c * (HWN / 4) + i * 2;

    float4 i0 = I[base], i1 = I[base + 1];
    int4  mi0 = mI4[i * 2], mi1 = mI4[i * 2 + 1];
    float4 j0 = J[base], j1 = J[base + 1];
    int4  mj0 = mJ4[i * 2], mj1 = mJ4[i * 2 + 1];

    int* cntI = g_cntI + c * FINE;
    int* cntJ = g_cntJ + c * FINE;
    {
        float vi[8] = {i0.x, i0.y, i0.z, i0.w, i1.x, i1.y, i1.z, i1.w};
        int   mi[8] = {mi0.x, mi0.y, mi0.z, mi0.w, mi1.x, mi1.y, mi1.z, mi1.w};
        float vj[8] = {j0.x, j0.y, j0.z, j0.w, j1.x, j1.y, j1.z, j1.w};
        int   mj[8] = {mj0.x, mj0.y, mj0.z, mj0.w, mj1.x, mj1.y, mj1.z, mj1.w};
        #pragma unroll
        for (int k = 0; k < 8; k++) {
            if (mi[k]) atomicAdd(&cntI[fbin(vi[k])], 1);
            if (mj[k]) atomicAdd(&cntJ[fbin(vj[k])], 1);
        }
    }

    // --- exact masked min/max of J ---
    float mn = 1e30f, mx = -1e30f;
    if (mj0.x) { mn = fminf(mn, j0.x); mx = fmaxf(mx, j0.x); }
    if (mj0.y) { mn = fminf(mn, j0.y); mx = fmaxf(mx, j0.y); }
    if (mj0.z) { mn = fminf(mn, j0.z); mx = fmaxf(mx, j0.z); }
    if (mj0.w) { mn = fminf(mn, j0.w); mx = fmaxf(mx, j0.w); }
    if (mj1.x) { mn = fminf(mn, j1.x); mx = fmaxf(mx, j1.x); }
    if (mj1.y) { mn = fminf(mn, j1.y); mx = fmaxf(mx, j1.y); }
    if (mj1.z) { mn = fminf(mn, j1.z); mx = fmaxf(mx, j1.z); }
    if (mj1.w) { mn = fminf(mn, j1.w); mx = fmaxf(mx, j1.w); }

    if (c == 0) {
        int sI = mi0.x + mi0.y + mi0.z + mi0.w + mi1.x + mi1.y + mi1.z + mi1.w;
        int sJ = mj0.x + mj0.y + mj0.z + mj0.w + mj1.x + mj1.y + mj1.z + mj1.w;
        for (int o = 16; o; o >>= 1) {
            sI += __shfl_down_sync(0xFFFFFFFFu, sI, o);
            sJ += __shfl_down_sync(0xFFFFFFFFu, sJ, o);
        }
        if ((threadIdx.x & 31) == 0) { atomicAdd(&g_nI, sI); atomicAdd(&g_nJ, sJ); }
    }

    for (int o = 16; o; o >>= 1) {
        mn = fminf(mn, __shfl_down_sync(0xFFFFFFFFu, mn, o));
        mx = fmaxf(mx, __shfl_down_sync(0xFFFFFFFFu, mx, o));
    }
    __shared__ float smn[8], smx[8];
    int t = threadIdx.x;
    if ((t & 31) == 0) { smn[t >> 5] = mn; smx[t >> 5] = mx; }
    __syncthreads();
    if (t < 8) {
        mn = smn[t]; mx = smx[t];
        for (int o = 4; o; o >>= 1) {
            mn = fminf(mn, __shfl_down_sync(0xFFu, mn, o));
            mx = fmaxf(mx, __shfl_down_sync(0xFFu, mx, o));
        }
        if (t == 0) {
            if (mn < 1e30f)  atomicMin(&g_minJ[c], __float_as_int(mn));
            if (mx > -1e30f) atomicMax(&g_maxJ[c], __float_as_int(mx));
        }
    }
}

// ---------------- K2: fused I-offset scan + fine->coarse J histogram -----------------
__global__ void k_mid() {
    int c = blockIdx.y, tile = blockIdx.x, t = threadIdx.x;   // 256 threads, 2048 bins
    __shared__ int shh[2 * NB];
    shh[t] = 0; shh[t + NB] = 0;
    __syncthreads();

    // --- J side: fold fine counts into coarse histogram (bin-center mapping) ---
    float minf = __int_as_float(g_minJ[c]);
    float maxf = __int_as_float(g_maxJ[c]);
    float step = (maxf - minf) * (1.0f / NB);
    float sden = fmaxf(step, 1e-12f);
    int baseJ = c * FINE + tile * TILEB + t * 8;
    int4 ja = *(const int4*)&g_cntJ[baseJ];
    int4 jb = *(const int4*)&g_cntJ[baseJ + 4];
    {
        int jc[8] = {ja.x, ja.y, ja.z, ja.w, jb.x, jb.y, jb.z, jb.w};
        int* h = shh + (t & 1) * NB;
        #pragma unroll
        for (int k = 0; k < 8; k++) {
            if (jc[k]) {
                float v = ((float)(tile * TILEB + t * 8 + k) + 0.5f) * WBIN;
                int b = (int)floorf((v - minf) / sden);
                b = max(0, min(NB - 1, b));
                atomicAdd(&h[b], jc[k]);
            }
        }
    }

    // --- I side: per-tile in-place exclusive scan of counts ---
    int base = c * FINE + tile * TILEB + t * 8;
    int4 a = *(const int4*)&g_cntI[base];
    int4 b4 = *(const int4*)&g_cntI[base + 4];
    int v[8] = {a.x, a.y, a.z, a.w, b4.x, b4.y, b4.z, b4.w};
    int loc[8];
    int run = 0;
    #pragma unroll
    for (int k = 0; k < 8; k++) { loc[k] = run; run += v[k]; }
    int lane = t & 31, wid = t >> 5;
    int x = run;
    for (int o = 1; o < 32; o <<= 1) {
        int u = __shfl_up_sync(0xFFFFFFFFu, x, o);
        if (lane >= o) x += u;
    }
    __shared__ int wsum[8];
    if (lane == 31) wsum[wid] = x;
    __syncthreads();
    if (t < 8) {
        int y = wsum[t];
        for (int o = 1; o < 8; o <<= 1) {
            int u = __shfl_up_sync(0xFFu, y, o);
            if (t >= o) y += u;
        }
        wsum[t] = y;
    }
    __syncthreads();
    int ex = x - run + (wid ? wsum[wid - 1] : 0);
    *(int4*)&g_cntI[base]     = make_int4(ex + loc[0], ex + loc[1], ex + loc[2], ex + loc[3]);
    *(int4*)&g_cntI[base + 4] = make_int4(ex + loc[4], ex + loc[5], ex + loc[6], ex + loc[7]);
    if (t == 255) g_tbase[c * NT + tile] = ex + run;    // tile total

    // --- flush coarse histogram ---
    __syncthreads();
    int s2 = shh[t] + shh[t + NB];
    if (s2) atomicAdd(&g_histJ[c * NB + t], s2);
}

// ---------------- K3: per-bin analytic loss (CDF + tile bases computed in-block) -----
__global__ void k_loss(float* __restrict__ out) {
    int c = blockIdx.y, tile = blockIdx.x, t = threadIdx.x;   // 256 threads, 8 bins each
    __shared__ float scum[NB], shis[NB], sh[NB];
    __shared__ int stb[NT + 1];
    // tile-base exclusive scan (warp 0, lanes 0..15)
    if (t < NT) {
        int tot = g_tbase[c * NT + t];
        int incl = tot;
        for (int o = 1; o < NT; o <<= 1) {
            int u = __shfl_up_sync(0xFFFFu, incl, o);
            if (t >= o) incl += u;
        }
        stb[t] = incl - tot;
        if (t == NT - 1) stb[NT] = incl;                 // channel total
    }
    // coarse CDF (redundant per block, trivial)
    float scale = (float)g_nI / (float)g_nJ;
    float h = (float)g_histJ[c * NB + t] * scale;
    shis[t] = h;
    sh[t] = h;
    __syncthreads();
    for (int o = 1; o < NB; o <<= 1) {
        float add = (t >= o) ? sh[t - o] : 0.0f;
        __syncthreads();
        sh[t] += add;
        __syncthreads();
    }
    scum[t] = sh[t];
    __syncthreads();

    float minf = __int_as_float(g_minJ[c]);
    float maxf = __int_as_float(g_maxJ[c]);
    float step = (maxf - minf) * (1.0f / NB);

    int base = c * FINE + tile * TILEB + t * 8;
    int4 a = *(const int4*)&g_cntI[base];
    int4 bq = *(const int4*)&g_cntI[base + 4];
    int o9[9] = {a.x, a.y, a.z, a.w, bq.x, bq.y, bq.z, bq.w, 0};
    int tb = stb[tile];
    if (t < 255) o9[8] = g_cntI[base + 8];
    int e_thread_last = (t < 255) ? (tb + o9[8]) : stb[tile + 1];

    double acc = 0.0;
    int bi = 0;
    bool first = true;
    #pragma unroll
    for (int k = 0; k < 8; k++) {
        int s = tb + o9[k];
        int e = (k < 7) ? (tb + o9[k + 1]) : e_thread_last;
        if (e <= s) continue;
        float xb = ((float)(tile * TILEB + t * 8 + k) + 0.5f) * WBIN;
        for (int p = s; p < e; p++) {
            float r = (float)(p + 1);
            if (first) {
                int pos = 0;
                #pragma unroll
                for (int st = 128; st > 0; st >>= 1) {
                    int np = pos + st;
                    if (np <= NB && scum[np - 1] < r) pos = np;
                }
                bi = pos > NB - 1 ? NB - 1 : pos;
                first = false;
            } else {
                while (bi < NB - 1 && scum[bi] < r) bi++;
            }
            float cJ = scum[bi], hb = shis[bi];
            float ratio = (r - (cJ - hb)) / fmaxf(hb, 1e-12f);
            ratio = fminf(fmaxf(ratio, 0.0f), 1.0f);
            float f = minf + ((float)bi + ratio) * step;
            float d = xb - f;
            acc += (double)d * (double)d;
        }
    }

    for (int o = 16; o; o >>= 1) acc += __shfl_down_sync(0xFFFFFFFFu, acc, o);
    __shared__ double sacc[8];
    if ((t & 31) == 0) sacc[t >> 5] = acc;
    __syncthreads();
    if (t < 8) {
        double v = sacc[t];
        for (int o = 4; o; o >>= 1) v += __shfl_down_sync(0xFFu, v, o);
        if (t == 0) {
            atomicAdd(&g_loss, v);
            __threadfence();
            unsigned int ticket = atomicAdd(&g_done, 1u);
            if (ticket == (unsigned)(CC * NT) - 1) {
                double tot = atomicAdd(&g_loss, 0.0);
                out[0] = (float)(tot * (100.0 / ((double)CC * (double)HWN)));
            }
        }
    }
}

extern "C" void kernel_launch(void* const* d_in, const int* in_sizes, int n_in,
                              void* d_out, int out_size) {
    const float* I = (const float*)d_in[0];
    const float* J = (const float*)d_in[1];
    const int*  mI = (const int*)d_in[2];
    const int*  mJ = (const int*)d_in[3];
    float* out = (float*)d_out;

    k_init<<<(CC * FINE / 4) / 1024, 1024>>>();

    dim3 g8((HWN / 8) / 256, CC);   // 128 x 64, 8 elems/thread
    k_pass1<<<g8, 256>>>((const float4*)I, (const float4*)J, (const int4*)mI, (const int4*)mJ);

    dim3 gs(NT, CC);                // 16 x 64
    k_mid<<<gs, 256>>>();
    k_loss<<<gs, 256>>>(out);
}

// round 12
// speedup vs baseline: 1.5202x; 1.5202x over previous
#include <cuda_runtime.h>
#include <cstdint>

#define CC 64
#define HWN 262144
#define NB 256
#define FINE 32768             // 2^15 fine bins per channel (lambda ~ 4)
#define WBIN (1.0f / (float)FINE)
#define TILEB 2048
#define NT (FINE / TILEB)      // 16 tiles per channel

// ---------------- scratch ----------------------------------------------------------
__device__ int            g_nI, g_nJ;
__device__ int            g_minJ[CC];    // float bits (values >= 0 -> int order == float order)
__device__ int            g_maxJ[CC];
__device__ int            g_histJ[CC * NB];
__device__ int            g_cntI[CC * FINE];     // counts -> (in place) tile-local offsets (8MB)
__device__ int            g_cntJ[CC * FINE];     // fine counts of masked J (8MB)
__device__ int            g_tbase[CC * NT];      // per-tile totals (scanned in k_loss)
__device__ double         g_loss;
__device__ unsigned int   g_done;

static __device__ __forceinline__ int fbin(float x) {
    int b = (int)(x * (float)FINE);
    return b < 0 ? 0 : (b > FINE - 1 ? FINE - 1 : b);
}

// ---------------- K0: init ----------------------------------------------------------
__global__ void k_init() {
    int i = blockIdx.x * blockDim.x + threadIdx.x;   // CC*FINE/4 threads
    ((int4*)g_cntI)[i] = make_int4(0, 0, 0, 0);
    ((int4*)g_cntJ)[i] = make_int4(0, 0, 0, 0);
    if (i < CC * NB) g_histJ[i] = 0;
    if (i < CC) { g_minJ[i] = 0x7F800000; g_maxJ[i] = 0; }
    if (i == 0) { g_nI = 0; g_nJ = 0; g_loss = 0.0; g_done = 0u; }
}

// ---------------- K1: single pass over I,J,masks ------------------------------------
__global__ void k_pass1(const float4* __restrict__ I, const float4* __restrict__ J,
                        const int4* __restrict__ mI4, const int4* __restrict__ mJ4) {
    int c = blockIdx.y;
    int i = blockIdx.x * blockDim.x + threadIdx.x;     // HWN/8 per channel
    int base = c * (HWN / 4) + i * 2;

    float4 i0 = I[base], i1 = I[base + 1];
    int4  mi0 = mI4[i * 2], mi1 = mI4[i * 2 + 1];
    float4 j0 = J[base], j1 = J[base + 1];
    int4  mj0 = mJ4[i * 2], mj1 = mJ4[i * 2 + 1];

    int* cntI = g_cntI + c * FINE;
    int* cntJ = g_cntJ + c * FINE;
    {
        float vi[8] = {i0.x, i0.y, i0.z, i0.w, i1.x, i1.y, i1.z, i1.w};
        int   mi[8] = {mi0.x, mi0.y, mi0.z, mi0.w, mi1.x, mi1.y, mi1.z, mi1.w};
        float vj[8] = {j0.x, j0.y, j0.z, j0.w, j1.x, j1.y, j1.z, j1.w};
        int   mj[8] = {mj0.x, mj0.y, mj0.z, mj0.w, mj1.x, mj1.y, mj1.z, mj1.w};
        #pragma unroll
        for (int k = 0; k < 8; k++) {
            if (mi[k]) atomicAdd(&cntI[fbin(vi[k])], 1);
            if (mj[k]) atomicAdd(&cntJ[fbin(vj[k])], 1);
        }
    }

    // --- exact masked min/max of J ---
    float mn = 1e30f, mx = -1e30f;
    if (mj0.x) { mn = fminf(mn, j0.x); mx = fmaxf(mx, j0.x); }
    if (mj0.y) { mn = fminf(mn, j0.y); mx = fmaxf(mx, j0.y); }
    if (mj0.z) { mn = fminf(mn, j0.z); mx = fmaxf(mx, j0.z); }
    if (mj0.w) { mn = fminf(mn, j0.w); mx = fmaxf(mx, j0.w); }
    if (mj1.x) { mn = fminf(mn, j1.x); mx = fmaxf(mx, j1.x); }
    if (mj1.y) { mn = fminf(mn, j1.y); mx = fmaxf(mx, j1.y); }
    if (mj1.z) { mn = fminf(mn, j1.z); mx = fmaxf(mx, j1.z); }
    if (mj1.w) { mn = fminf(mn, j1.w); mx = fmaxf(mx, j1.w); }

    if (c == 0) {
        int sI = mi0.x + mi0.y + mi0.z + mi0.w + mi1.x + mi1.y + mi1.z + mi1.w;
        int sJ = mj0.x + mj0.y + mj0.z + mj0.w + mj1.x + mj1.y + mj1.z + mj1.w;
        for (int o = 16; o; o >>= 1) {
            sI += __shfl_down_sync(0xFFFFFFFFu, sI, o);
            sJ += __shfl_down_sync(0xFFFFFFFFu, sJ, o);
        }
        if ((threadIdx.x & 31) == 0) { atomicAdd(&g_nI, sI); atomicAdd(&g_nJ, sJ); }
    }

    for (int o = 16; o; o >>= 1) {
        mn = fminf(mn, __shfl_down_sync(0xFFFFFFFFu, mn, o));
        mx = fmaxf(mx, __shfl_down_sync(0xFFFFFFFFu, mx, o));
    }
    __shared__ float smn[8], smx[8];
    int t = threadIdx.x;
    if ((t & 31) == 0) { smn[t >> 5] = mn; smx[t >> 5] = mx; }
    __syncthreads();
    if (t < 8) {
        mn = smn[t]; mx = smx[t];
        for (int o = 4; o; o >>= 1) {
            mn = fminf(mn, __shfl_down_sync(0xFFu, mn, o));
            mx = fmaxf(mx, __shfl_down_sync(0xFFu, mx, o));
        }
        if (t == 0) {
            if (mn < 1e30f)  atomicMin(&g_minJ[c], __float_as_int(mn));
            if (mx > -1e30f) atomicMax(&g_maxJ[c], __float_as_int(mx));
        }
    }
}

// ---------------- K2: fused I-offset scan + fine->coarse J histogram -----------------
__global__ void k_mid() {
    int c = blockIdx.y, tile = blockIdx.x, t = threadIdx.x;   // 256 threads, 2048 bins
    __shared__ int shh[2 * NB];
    shh[t] = 0; shh[t + NB] = 0;
    __syncthreads();

    float minf = __int_as_float(g_minJ[c]);
    float maxf = __int_as_float(g_maxJ[c]);
    float step = (maxf - minf) * (1.0f / NB);
    float sden = fmaxf(step, 1e-12f);
    int baseJ = c * FINE + tile * TILEB + t * 8;
    int4 ja = *(const int4*)&g_cntJ[baseJ];
    int4 jb = *(const int4*)&g_cntJ[baseJ + 4];
    {
        int jc[8] = {ja.x, ja.y, ja.z, ja.w, jb.x, jb.y, jb.z, jb.w};
        int* h = shh + (t & 1) * NB;
        #pragma unroll
        for (int k = 0; k < 8; k++) {
            if (jc[k]) {
                float v = ((float)(tile * TILEB + t * 8 + k) + 0.5f) * WBIN;
                int b = (int)floorf((v - minf) / sden);
                b = max(0, min(NB - 1, b));
                atomicAdd(&h[b], jc[k]);
            }
        }
    }

    int base = c * FINE + tile * TILEB + t * 8;
    int4 a = *(const int4*)&g_cntI[base];
    int4 b4 = *(const int4*)&g_cntI[base + 4];
    int v[8] = {a.x, a.y, a.z, a.w, b4.x, b4.y, b4.z, b4.w};
    int loc[8];
    int run = 0;
    #pragma unroll
    for (int k = 0; k < 8; k++) { loc[k] = run; run += v[k]; }
    int lane = t & 31, wid = t >> 5;
    int x = run;
    for (int o = 1; o < 32; o <<= 1) {
        int u = __shfl_up_sync(0xFFFFFFFFu, x, o);
        if (lane >= o) x += u;
    }
    __shared__ int wsum[8];
    if (lane == 31) wsum[wid] = x;
    __syncthreads();
    if (t < 8) {
        int y = wsum[t];
        for (int o = 1; o < 8; o <<= 1) {
            int u = __shfl_up_sync(0xFFu, y, o);
            if (t >= o) y += u;
        }
        wsum[t] = y;
    }
    __syncthreads();
    int ex = x - run + (wid ? wsum[wid - 1] : 0);
    *(int4*)&g_cntI[base]     = make_int4(ex + loc[0], ex + loc[1], ex + loc[2], ex + loc[3]);
    *(int4*)&g_cntI[base + 4] = make_int4(ex + loc[4], ex + loc[5], ex + loc[6], ex + loc[7]);
    if (t == 255) g_tbase[c * NT + tile] = ex + run;

    __syncthreads();
    int s2 = shh[t] + shh[t + NB];
    if (s2) atomicAdd(&g_histJ[c * NB + t], s2);
}

// ---------------- K3: per-bin analytic loss, register-affine rank walk ---------------
__global__ void k_loss(float* __restrict__ out) {
    int c = blockIdx.y, tile = blockIdx.x, t = threadIdx.x;   // 256 threads, 8 bins each
    __shared__ float scum[NB], shis[NB], sh[NB];
    __shared__ int stb[NT + 1];
    if (t < NT) {
        int tot = g_tbase[c * NT + t];
        int incl = tot;
        for (int o = 1; o < NT; o <<= 1) {
            int u = __shfl_up_sync(0xFFFFu, incl, o);
            if (t >= o) incl += u;
        }
        stb[t] = incl - tot;
        if (t == NT - 1) stb[NT] = incl;                 // channel total
    }
    float scale = (float)g_nI / (float)g_nJ;
    float h = (float)g_histJ[c * NB + t] * scale;
    shis[t] = h;
    sh[t] = h;
    __syncthreads();
    for (int o = 1; o < NB; o <<= 1) {
        float add = (t >= o) ? sh[t - o] : 0.0f;
        __syncthreads();
        sh[t] += add;
        __syncthreads();
    }
    scum[t] = sh[t];
    __syncthreads();

    float minf = __int_as_float(g_minJ[c]);
    float maxf = __int_as_float(g_maxJ[c]);
    float step = (maxf - minf) * (1.0f / NB);

    int base = c * FINE + tile * TILEB + t * 8;
    int4 a = *(const int4*)&g_cntI[base];
    int4 bq = *(const int4*)&g_cntI[base + 4];
    int o9[9] = {a.x, a.y, a.z, a.w, bq.x, bq.y, bq.z, bq.w, 0};
    int tb = stb[tile];
    if (t < 255) o9[8] = g_cntI[base + 8];
    int e_thread_last = (t < 255) ? (tb + o9[8]) : stb[tile + 1];

    // register-resident coarse-bin segment state
    int bi = -1;
    float bndry = 0.0f, lo = 0.0f, invh = 0.0f, fb = 0.0f;
    float facc = 0.0f;                                   // f32 accumulator (4-cyc chain)

    #pragma unroll
    for (int k = 0; k < 8; k++) {
        int s = tb + o9[k];
        int e = (k < 7) ? (tb + o9[k + 1]) : e_thread_last;
        if (e <= s) continue;
        float xb = ((float)(tile * TILEB + t * 8 + k) + 0.5f) * WBIN;
        for (int p = s; p < e; p++) {
            float r = (float)(p + 1);
            if (bi < 0) {                                // one binary search per thread
                int pos = 0;
                #pragma unroll
                for (int st = 128; st > 0; st >>= 1) {
                    int np = pos + st;
                    if (np <= NB && scum[np - 1] < r) pos = np;
                }
                bi = pos > NB - 1 ? NB - 1 : pos;
                float cJ = scum[bi], hb = shis[bi];
                bndry = cJ; lo = cJ - hb;
                invh = 1.0f / fmaxf(hb, 1e-12f);
                fb = minf + (float)bi * step;
            } else {
                while (r > bndry && bi < NB - 1) {       // rare: coarse-bin crossing
                    bi++;
                    float cJ = scum[bi], hb = shis[bi];
                    bndry = cJ; lo = cJ - hb;
                    invh = 1.0f / fmaxf(hb, 1e-12f);
                    fb = minf + (float)bi * step;
                }
            }
            float ratio = (r - lo) * invh;
            ratio = fminf(fmaxf(ratio, 0.0f), 1.0f);
            float f = fb + ratio * step;
            float d = xb - f;
            facc = fmaf(d, d, facc);
        }
    }

    double acc = (double)facc;
    for (int o = 16; o; o >>= 1) acc += __shfl_down_sync(0xFFFFFFFFu, acc, o);
    __shared__ double sacc[8];
    if ((t & 31) == 0) sacc[t >> 5] = acc;
    __syncthreads();
    if (t < 8) {
        double v = sacc[t];
        for (int o = 4; o; o >>= 1) v += __shfl_down_sync(0xFFu, v, o);
        if (t == 0) {
            atomicAdd(&g_loss, v);
            __threadfence();
            unsigned int ticket = atomicAdd(&g_done, 1u);
            if (ticket == (unsigned)(CC * NT) - 1) {
                double tot = atomicAdd(&g_loss, 0.0);
                out[0] = (float)(tot * (100.0 / ((double)CC * (double)HWN)));
            }
        }
    }
}

extern "C" void kernel_launch(void* const* d_in, const int* in_sizes, int n_in,
                              void* d_out, int out_size) {
    const float* I = (const float*)d_in[0];
    const float* J = (const float*)d_in[1];
    const int*  mI = (const int*)d_in[2];
    const int*  mJ = (const int*)d_in[3];
    float* out = (float*)d_out;

    k_init<<<(CC * FINE / 4) / 1024, 1024>>>();

    dim3 g8((HWN / 8) / 256, CC);   // 128 x 64, 8 elems/thread
    k_pass1<<<g8, 256>>>((const float4*)I, (const float4*)J, (const int4*)mI, (const int4*)mJ);

    dim3 gs(NT, CC);                // 16 x 64
    k_mid<<<gs, 256>>>();
    k_loss<<<gs, 256>>>(out);
}

// round 13
// speedup vs baseline: 1.9954x; 1.3126x over previous
#include <cuda_runtime.h>
#include <cstdint>

#define CC 64
#define HWN 262144
#define NB 256
#define FINE 32768             // 2^15 fine bins per channel (lambda ~ 4)
#define WBIN (1.0f / (float)FINE)
#define TILEB 2048
#define NT (FINE / TILEB)      // 16 tiles per channel

// ---------------- scratch ----------------------------------------------------------
__device__ int            g_nI, g_nJ;
__device__ int            g_minJ[CC];    // float bits (values >= 0 -> int order == float order)
__device__ int            g_maxJ[CC];
__device__ int            g_histJ[CC * NB];
__device__ int            g_cntI[CC * FINE];     // counts -> (in place) tile-local offsets (8MB)
__device__ int            g_tbase[CC * NT];      // per-tile totals (scanned in k_loss)
__device__ double         g_loss;
__device__ unsigned int   g_done;

static __device__ __forceinline__ int fbin(float x) {
    int b = (int)(x * (float)FINE);
    return b < 0 ? 0 : (b > FINE - 1 ? FINE - 1 : b);
}

// ---------------- K0: init ----------------------------------------------------------
__global__ void k_init() {
    int i = blockIdx.x * blockDim.x + threadIdx.x;   // CC*FINE/4 threads
    ((int4*)g_cntI)[i] = make_int4(0, 0, 0, 0);
    if (i < CC * NB) g_histJ[i] = 0;
    if (i < CC) { g_minJ[i] = 0x7F800000; g_maxJ[i] = 0; }
    if (i == 0) { g_nI = 0; g_nJ = 0; g_loss = 0.0; g_done = 0u; }
}

// ---------------- K1: minmax(J) + nJ (pure BW pass) ----------------------------------
__global__ void k_passJmm(const float4* __restrict__ J, const int4* __restrict__ mJ4) {
    int c = blockIdx.y;
    int i = blockIdx.x * blockDim.x + threadIdx.x;     // HWN/8 per channel
    int base = c * (HWN / 4) + i * 2;
    float4 j0 = J[base], j1 = J[base + 1];
    int4  mj0 = mJ4[i * 2], mj1 = mJ4[i * 2 + 1];

    float mn = 1e30f, mx = -1e30f;
    if (mj0.x) { mn = fminf(mn, j0.x); mx = fmaxf(mx, j0.x); }
    if (mj0.y) { mn = fminf(mn, j0.y); mx = fmaxf(mx, j0.y); }
    if (mj0.z) { mn = fminf(mn, j0.z); mx = fmaxf(mx, j0.z); }
    if (mj0.w) { mn = fminf(mn, j0.w); mx = fmaxf(mx, j0.w); }
    if (mj1.x) { mn = fminf(mn, j1.x); mx = fmaxf(mx, j1.x); }
    if (mj1.y) { mn = fminf(mn, j1.y); mx = fmaxf(mx, j1.y); }
    if (mj1.z) { mn = fminf(mn, j1.z); mx = fmaxf(mx, j1.z); }
    if (mj1.w) { mn = fminf(mn, j1.w); mx = fmaxf(mx, j1.w); }

    if (c == 0) {
        int sJ = mj0.x + mj0.y + mj0.z + mj0.w + mj1.x + mj1.y + mj1.z + mj1.w;
        for (int o = 16; o; o >>= 1) sJ += __shfl_down_sync(0xFFFFFFFFu, sJ, o);
        if ((threadIdx.x & 31) == 0) atomicAdd(&g_nJ, sJ);
    }
    for (int o = 16; o; o >>= 1) {
        mn = fminf(mn, __shfl_down_sync(0xFFFFFFFFu, mn, o));
        mx = fmaxf(mx, __shfl_down_sync(0xFFFFFFFFu, mx, o));
    }
    __shared__ float smn[8], smx[8];
    int t = threadIdx.x;
    if ((t & 31) == 0) { smn[t >> 5] = mn; smx[t >> 5] = mx; }
    __syncthreads();
    if (t < 8) {
        mn = smn[t]; mx = smx[t];
        for (int o = 4; o; o >>= 1) {
            mn = fminf(mn, __shfl_down_sync(0xFFu, mn, o));
            mx = fmaxf(mx, __shfl_down_sync(0xFFu, mx, o));
        }
        if (t == 0) {
            if (mn < 1e30f)  atomicMin(&g_minJ[c], __float_as_int(mn));
            if (mx > -1e30f) atomicMax(&g_maxJ[c], __float_as_int(mx));
        }
    }
}

// ---------------- K2 (aux stream): exact coarse histogram of J (4-replica shared) ----
__global__ void k_histJ(const float4* __restrict__ J, const int4* __restrict__ mJ4) {
    __shared__ int sh[4 * NB];
    int c = blockIdx.y;
    int t = threadIdx.x;
    #pragma unroll
    for (int k = 0; k < 4; k++) sh[k * NB + t] = 0;
    __syncthreads();
    float minf = __int_as_float(g_minJ[c]);
    float maxf = __int_as_float(g_maxJ[c]);
    float step = (maxf - minf) * (1.0f / NB);
    float sden = fmaxf(step, 1e-12f);
    int i = blockIdx.x * blockDim.x + t;
    int base = c * (HWN / 4) + i * 2;
    float4 v0 = J[base], v1 = J[base + 1];
    int4  m0 = mJ4[i * 2], m1 = mJ4[i * 2 + 1];
    int* h = sh + (t & 3) * NB;
    #define HADD(mm, vv) if (mm) { int b = (int)floorf((vv - minf) / sden); b = max(0, min(NB - 1, b)); atomicAdd(&h[b], 1); }
    HADD(m0.x, v0.x) HADD(m0.y, v0.y) HADD(m0.z, v0.z) HADD(m0.w, v0.w)
    HADD(m1.x, v1.x) HADD(m1.y, v1.y) HADD(m1.z, v1.z) HADD(m1.w, v1.w)
    #undef HADD
    __syncthreads();
    int s = sh[t] + sh[NB + t] + sh[2 * NB + t] + sh[3 * NB + t];
    if (s) atomicAdd(&g_histJ[c * NB + t], s);
}

// ---------------- K3 (main stream): fine-count I + nI ---------------------------------
__global__ void k_passI(const float4* __restrict__ I, const int4* __restrict__ mI4) {
    int c = blockIdx.y;
    int i = blockIdx.x * blockDim.x + threadIdx.x;
    int base = c * (HWN / 4) + i * 2;
    float4 i0 = I[base], i1 = I[base + 1];
    int4  mi0 = mI4[i * 2], mi1 = mI4[i * 2 + 1];

    int* cnt = g_cntI + c * FINE;
    #define FC(mm, vv) if (mm) atomicAdd(&cnt[fbin(vv)], 1);
    FC(mi0.x, i0.x) FC(mi0.y, i0.y) FC(mi0.z, i0.z) FC(mi0.w, i0.w)
    FC(mi1.x, i1.x) FC(mi1.y, i1.y) FC(mi1.z, i1.z) FC(mi1.w, i1.w)
    #undef FC

    if (c == 0) {
        int sI = mi0.x + mi0.y + mi0.z + mi0.w + mi1.x + mi1.y + mi1.z + mi1.w;
        for (int o = 16; o; o >>= 1) sI += __shfl_down_sync(0xFFFFFFFFu, sI, o);
        if ((threadIdx.x & 31) == 0) atomicAdd(&g_nI, sI);
    }
}

// ---------------- K4: per-tile in-place exclusive scan of I counts -------------------
__global__ void k_mid() {
    int c = blockIdx.y, tile = blockIdx.x, t = threadIdx.x;   // 256 threads, 2048 bins
    int base = c * FINE + tile * TILEB + t * 8;
    int4 a = *(const int4*)&g_cntI[base];
    int4 b4 = *(const int4*)&g_cntI[base + 4];
    int v[8] = {a.x, a.y, a.z, a.w, b4.x, b4.y, b4.z, b4.w};
    int loc[8];
    int run = 0;
    #pragma unroll
    for (int k = 0; k < 8; k++) { loc[k] = run; run += v[k]; }
    int lane = t & 31, wid = t >> 5;
    int x = run;
    for (int o = 1; o < 32; o <<= 1) {
        int u = __shfl_up_sync(0xFFFFFFFFu, x, o);
        if (lane >= o) x += u;
    }
    __shared__ int wsum[8];
    if (lane == 31) wsum[wid] = x;
    __syncthreads();
    if (t < 8) {
        int y = wsum[t];
        for (int o = 1; o < 8; o <<= 1) {
            int u = __shfl_up_sync(0xFFu, y, o);
            if (t >= o) y += u;
        }
        wsum[t] = y;
    }
    __syncthreads();
    int ex = x - run + (wid ? wsum[wid - 1] : 0);
    *(int4*)&g_cntI[base]     = make_int4(ex + loc[0], ex + loc[1], ex + loc[2], ex + loc[3]);
    *(int4*)&g_cntI[base + 4] = make_int4(ex + loc[4], ex + loc[5], ex + loc[6], ex + loc[7]);
    if (t == 255) g_tbase[c * NT + tile] = ex + run;
}

// ---------------- K5: closed-form per-bin loss ----------------------------------------
__global__ void k_loss(float* __restrict__ out) {
    int c = blockIdx.y, tile = blockIdx.x, t = threadIdx.x;   // 256 threads, 8 bins each
    __shared__ float scum[NB], shis[NB], sh[NB];
    __shared__ int stb[NT + 1];
    if (t < NT) {
        int tot = g_tbase[c * NT + t];
        int incl = tot;
        for (int o = 1; o < NT; o <<= 1) {
            int u = __shfl_up_sync(0xFFFFu, incl, o);
            if (t >= o) incl += u;
        }
        stb[t] = incl - tot;
        if (t == NT - 1) stb[NT] = incl;                 // channel total
    }
    float scale = (float)g_nI / (float)g_nJ;
    float h = (float)g_histJ[c * NB + t] * scale;
    shis[t] = h;
    sh[t] = h;
    __syncthreads();
    for (int o = 1; o < NB; o <<= 1) {
        float add = (t >= o) ? sh[t - o] : 0.0f;
        __syncthreads();
        sh[t] += add;
        __syncthreads();
    }
    scum[t] = sh[t];
    __syncthreads();

    float minf = __int_as_float(g_minJ[c]);
    float maxf = __int_as_float(g_maxJ[c]);
    float step = (maxf - minf) * (1.0f / NB);

    int base = c * FINE + tile * TILEB + t * 8;
    int4 a = *(const int4*)&g_cntI[base];
    int4 bq = *(const int4*)&g_cntI[base + 4];
    int o9[9] = {a.x, a.y, a.z, a.w, bq.x, bq.y, bq.z, bq.w, 0};
    int tb = stb[tile];
    if (t < 255) o9[8] = g_cntI[base + 8];
    int e_thread_last = (t < 255) ? (tb + o9[8]) : stb[tile + 1];

    // register-resident coarse-bin segment state
    int bi = -1;
    float cum_bi = 0.0f, lo = 0.0f, invh = 0.0f, fb = 0.0f;
    float acc = 0.0f;

    for (int k = 0; k < 8; k++) {
        int s = tb + o9[k];
        int e = (k < 7) ? (tb + o9[k + 1]) : e_thread_last;
        if (e <= s) continue;
        float xb = ((float)(tile * TILEB + t * 8 + k) + 0.5f) * WBIN;  // bin center
        int r0 = s + 1;
        while (r0 <= e) {
            if (bi < 0) {                                // one binary search per thread
                float r = (float)r0;
                int pos = 0;
                #pragma unroll
                for (int st = 128; st > 0; st >>= 1) {
                    int np = pos + st;
                    if (np <= NB && scum[np - 1] < r) pos = np;
                }
                bi = pos > NB - 1 ? NB - 1 : pos;
                cum_bi = scum[bi]; float hb = shis[bi];
                lo = cum_bi - hb; invh = 1.0f / fmaxf(hb, 1e-12f);
                fb = minf + (float)bi * step;
            } else {
                while ((float)r0 > cum_bi && bi < NB - 1) {
                    bi++;
                    cum_bi = scum[bi]; float hb = shis[bi];
                    lo = cum_bi - hb; invh = 1.0f / fmaxf(hb, 1e-12f);
                    fb = minf + (float)bi * step;
                }
            }
            if (bi == NB - 1 && (float)r0 > cum_bi) {    // clamp region: ratio = 1
                float d = xb - (fb + step);
                float fn = (float)(e - r0 + 1);
                acc = fmaf(fn * d, d, acc);
                r0 = e + 1;
                continue;
            }
            int rend = e;
            if ((float)e > cum_bi) {
                int rb = (int)floorf(cum_bi);
                rend = rb < e ? rb : e;                  // rb >= r0 since cum_bi >= r0
            }
            // d(i) = a0 + q*i over i = 0..n-1
            float a0 = xb - fb - ((float)r0 - lo) * invh * step;
            float q  = -invh * step;
            float fn = (float)(rend - r0 + 1);
            float s1 = 0.5f * fn * (fn - 1.0f);
            float s2 = (fn - 1.0f) * fn * (2.0f * fn - 1.0f) * (1.0f / 6.0f);
            acc += fn * a0 * a0 + 2.0f * a0 * q * s1 + q * q * s2;
            r0 = rend + 1;
        }
    }

    double dacc = (double)acc;
    for (int o = 16; o; o >>= 1) dacc += __shfl_down_sync(0xFFFFFFFFu, dacc, o);
    __shared__ double sacc[8];
    if ((t & 31) == 0) sacc[t >> 5] = dacc;
    __syncthreads();
    if (t < 8) {
        double v = sacc[t];
        for (int o = 4; o; o >>= 1) v += __shfl_down_sync(0xFFu, v, o);
        if (t == 0) {
            atomicAdd(&g_loss, v);
            __threadfence();
            unsigned int ticket = atomicAdd(&g_done, 1u);
            if (ticket == (unsigned)(CC * NT) - 1) {
                double tot = atomicAdd(&g_loss, 0.0);
                out[0] = (float)(tot * (100.0 / ((double)CC * (double)HWN)));
            }
        }
    }
}

extern "C" void kernel_launch(void* const* d_in, const int* in_sizes, int n_in,
                              void* d_out, int out_size) {
    const float* I = (const float*)d_in[0];
    const float* J = (const float*)d_in[1];
    const int*  mI = (const int*)d_in[2];
    const int*  mJ = (const int*)d_in[3];
    float* out = (float*)d_out;

    static cudaStream_t s_aux = nullptr;
    static cudaEvent_t  ev_fork = nullptr, ev_join = nullptr;
    if (!s_aux) {
        cudaStreamCreateWithFlags(&s_aux, cudaStreamNonBlocking);
        cudaEventCreateWithFlags(&ev_fork, cudaEventDisableTiming);
        cudaEventCreateWithFlags(&ev_join, cudaEventDisableTiming);
    }

    k_init<<<(CC * FINE / 4) / 1024, 1024>>>();

    dim3 g8((HWN / 8) / 256, CC);   // 128 x 64, 8 elems/thread
    k_passJmm<<<g8, 256>>>((const float4*)J, (const int4*)mJ);

    // fork: exact coarse histJ on aux stream (shared-atomic/LSU-bound),
    // concurrent with the L2-atomic-bound I-count pass on the main stream
    cudaEventRecord(ev_fork, 0);
    cudaStreamWaitEvent(s_aux, ev_fork, 0);
    k_histJ<<<g8, 256, 0, s_aux>>>((const float4*)J, (const int4*)mJ);
    cudaEventRecord(ev_join, s_aux);

    k_passI<<<g8, 256>>>((const float4*)I, (const int4*)mI);

    dim3 gs(NT, CC);                // 16 x 64
    k_mid<<<gs, 256>>>();

    cudaStreamWaitEvent(0, ev_join, 0);
    k_loss<<<gs, 256>>>(out);
}